// round 16
// baseline (speedup 1.0000x reference)
#include <cuda_runtime.h>

// HMM forward: alpha_t = (alpha_{t-1} @ A) * B[:, obs_t],  out = sum(alpha_{T-1})
// R16 = R6 with the detect->consume pipeline deepened from 2 to 4 stages per
// half (chunk groups of 4, consumed at k-granularity 2). The poll keeps the
// full MLP-8 batch in flight (phase 1 exits on chunks 0-3; phase 2 first
// checks chunks 4-7 from the same batch), so no extra L2 round is added —
// only the early group's restripe+arrive is hoisted ahead of late chunks.
// All other R6 invariants (publish line ownership, poll traffic/cadence,
// SMEM bytes, roles, pair barrier) unchanged.

namespace {
constexpr int GRID = 128;
constexpr int NT   = 256;
constexpr int S    = 2048;
constexpr int V    = 32768;
constexpr int T    = 4096;
constexpr int NCOL = 16;      // columns per block
}

typedef unsigned long long u64;

// Each uint4 = two elements: (val0, tag0, val1, tag1). 3 rotating buffers.
__device__ uint4    g_alpha3[3][S / 2];
__device__ unsigned g_epoch = 0;
__device__ unsigned g_done  = 0;

__device__ __forceinline__ uint4 ld_vol4(const uint4* p) {
    uint4 v;
    asm volatile("ld.volatile.global.v4.u32 {%0,%1,%2,%3}, [%4];"
                 : "=r"(v.x), "=r"(v.y), "=r"(v.z), "=r"(v.w) : "l"(p) : "memory");
    return v;
}
__device__ __forceinline__ void st_cg_v2(void* p, unsigned a, unsigned b) {
    asm volatile("st.global.cg.v2.u32 [%0], {%1,%2};" :: "l"(p), "r"(a), "r"(b) : "memory");
}
__device__ __forceinline__ u64 pack2(float a, float b) {
    u64 d;
    asm("mov.b64 %0, {%1,%2};" : "=l"(d) : "f"(a), "f"(b));
    return d;
}
__device__ __forceinline__ u64 fma2(u64 a, u64 b, u64 c) {
    u64 d;
    asm("fma.rn.f32x2 %0, %1, %2, %3;" : "=l"(d) : "l"(a), "l"(b), "l"(c));
    return d;
}
__device__ __forceinline__ u64 add2(u64 a, u64 b) {
    u64 d;
    asm("add.rn.f32x2 %0, %1, %2;" : "=l"(d) : "l"(a), "l"(b));
    return d;
}

__global__ void __launch_bounds__(NT, 1) hmm_forward_kernel(
    const int*   __restrict__ obs,
    const float* __restrict__ A,
    const float* __restrict__ B,
    const float* __restrict__ pi,
    float*       __restrict__ out)
{
    __shared__ __align__(16) float alpha_sm[2][2][1024]; // [parity][half][elem]
    __shared__ __align__(16) float red[2][2][NCOL];      // [parity][rowgroup][col]

    const int tid  = threadIdx.x;
    const int blk  = blockIdx.x;
    const int w    = tid >> 5;
    const int lane = tid & 31;
    const int cg   = w & 3;               // column group 0..3 (4 cols each)
    const int rg   = w >> 2;              // row group 0..1 (half = 1024 rows)
    const int jb   = blk * NCOL + cg * 4; // first of this warp's 4 columns

    // Pollers: w2 (h0 chunks 0-7 -> stages 0,1), w3 (h0 chunks 8-15 -> stages 2,3),
    //          w4 (h1 stages 0,1), w5 (h1 stages 2,3).
    const bool is_poller = (w >= 2) && (w <= 5);
    const int  poll_half = (w <= 3) ? 0 : 1;
    const bool owns_lo   = (w == 2 || w == 4);   // chunks 0-7 of its half
    const int  chunk_off = owns_lo ? 0 : 8;
    // Stage barriers: half0 -> bars 1..4 (stages 0..3); half1 -> bars 5..8.
    // A warp's compute half is rg; stage barrier = 1 + rg*4 + stage.
    const int  sbase = 1 + rg * 4;
    // Stage ownership mask for this warp (pollers own 2 stages of their half;
    // note poll_half == rg for all pollers).
    const unsigned own_mask = is_poller ? (owns_lo ? 0x3u : 0xCu) : 0x0u;
    // Epilogue warp per pair (cg): pair0->w0, pair1->w1, pair2->w6, pair3->w7.
    const bool is_epi = (rg == 0) ? (cg <= 1) : (cg >= 2);

    // ---- Load A tile into packed-pair registers (one time) ----
    // Thread covers rows rg*1024 + 4*lane + 128*k + rr (k<8, rr<4), cols jb..jb+3.
    u64 areg_lo[8][4], areg_hi[8][4];
#pragma unroll
    for (int k = 0; k < 8; k++) {
#pragma unroll
        for (int rr = 0; rr < 4; rr++) {
            int row = rg * 1024 + 4 * lane + 128 * k + rr;
            float4 a4 = *reinterpret_cast<const float4*>(&A[(size_t)row * S + jb]);
            areg_lo[k][rr] = pack2(a4.x, a4.y);
            areg_hi[k][rr] = pack2(a4.z, a4.w);
        }
    }

    const unsigned epoch = *(volatile unsigned*)&g_epoch;
    const unsigned tagbase = epoch * 4096u + 1u;   // >0, unique across replays

    if (blk == 0 && tid == 0) *out = 0.0f;

    // ---- Publish alpha_0 = pi * B[:, obs[0]] with tag(0) ----
    if (is_epi && lane < 4) {
        int   c  = jb + lane;
        int   o0 = __ldg(&obs[0]);
        float v  = pi[c] * __ldg(&B[(size_t)c * V + o0]);
        st_cg_v2(reinterpret_cast<char*>(g_alpha3[0]) + (size_t)c * 8,
                 __float_as_uint(v), tagbase);
    }

    for (int s = 1; s < T; s++) {
        const int      par  = s & 1;
        const int      bufR = (s - 1) % 3;
        const int      bufW = s % 3;
        const unsigned tagR = tagbase + (unsigned)(s - 1);
        const unsigned tagW = tagbase + (unsigned)s;

        // Epilogue lanes prefetch their emission factor (independent of alpha).
        float bj = 0.0f;
        if (is_epi && lane < 4) {
            int o = __ldg(&obs[s]);
            bj = __ldg(&B[(size_t)(jb + lane) * V + o]);
        }

        // ---- Pollers: two-phase detect (full MLP-8 batch), staged restripe ----
        if (is_poller) {
            const uint4* base = &g_alpha3[bufR][poll_half * 512] + chunk_off * 32 + lane;
            uint4 v[8];
            // Phase 1: poll all 8 chunks; exit when chunks 0-3 are ready.
            for (;;) {
                bool ok = true;
#pragma unroll
                for (int c = 0; c < 8; c++) v[c] = ld_vol4(base + c * 32);
#pragma unroll
                for (int c = 0; c < 4; c++) ok &= (v[c].y == tagR) & (v[c].w == tagR);
                if (__all_sync(0xffffffffu, ok)) break;
            }
#pragma unroll
            for (int c = 0; c < 4; c++) {
                float2 f = make_float2(__uint_as_float(v[c].x), __uint_as_float(v[c].z));
                *reinterpret_cast<float2*>(
                    &alpha_sm[par][poll_half][(chunk_off + c) * 64 + 2 * lane]) = f;
            }
            asm volatile("bar.arrive %0, 128;" :: "r"(sbase + (owns_lo ? 0 : 2)) : "memory");
            // Phase 2: chunks 4-7 — check the already-loaded batch first.
            for (;;) {
                bool ok = true;
#pragma unroll
                for (int c = 4; c < 8; c++) ok &= (v[c].y == tagR) & (v[c].w == tagR);
                if (__all_sync(0xffffffffu, ok)) break;
#pragma unroll
                for (int c = 4; c < 8; c++) v[c] = ld_vol4(base + c * 32);
            }
#pragma unroll
            for (int c = 4; c < 8; c++) {
                float2 f = make_float2(__uint_as_float(v[c].x), __uint_as_float(v[c].z));
                *reinterpret_cast<float2*>(
                    &alpha_sm[par][poll_half][(chunk_off + c) * 64 + 2 * lane]) = f;
            }
            asm volatile("bar.arrive %0, 128;" :: "r"(sbase + (owns_lo ? 1 : 3)) : "memory");
        }

        const float4* sm4 = reinterpret_cast<const float4*>(alpha_sm[par][rg]);
        u64 acc01 = 0, acc23 = 0;   // packed (col0,col1), (col2,col3)

        // ---- Staged matvec: stage st consumes k = 2st, 2st+1 ----
#pragma unroll
        for (int st = 0; st < 4; st++) {
            if (!(own_mask & (1u << st)))
                asm volatile("bar.sync %0, 128;" :: "r"(sbase + st) : "memory");
#pragma unroll
            for (int kk = 0; kk < 2; kk++) {
                int k = 2 * st + kk;
                float4 av = sm4[k * 32 + lane];
                u64 ax = pack2(av.x, av.x), ay = pack2(av.y, av.y);
                u64 az = pack2(av.z, av.z), aw = pack2(av.w, av.w);
                acc01 = fma2(ax, areg_lo[k][0], acc01);
                acc23 = fma2(ax, areg_hi[k][0], acc23);
                acc01 = fma2(ay, areg_lo[k][1], acc01);
                acc23 = fma2(ay, areg_hi[k][1], acc23);
                acc01 = fma2(az, areg_lo[k][2], acc01);
                acc23 = fma2(az, areg_hi[k][2], acc23);
                acc01 = fma2(aw, areg_lo[k][3], acc01);
                acc23 = fma2(aw, areg_hi[k][3], acc23);
            }
        }

        // Warp reduce (rows split across lanes) on packed pairs.
#pragma unroll
        for (int off = 16; off > 0; off >>= 1) {
            acc01 = add2(acc01, __shfl_xor_sync(0xffffffffu, acc01, off));
            acc23 = add2(acc23, __shfl_xor_sync(0xffffffffu, acc23, off));
        }
        if (lane == 0) {
            u64* r = reinterpret_cast<u64*>(&red[par][rg][cg * 4]);
            r[0] = acc01;
            r[1] = acc23;
        }

        // Pair-scoped barrier: warps (cg, cg+4) on bar 9+cg, 64 threads.
        asm volatile("bar.sync %0, 64;" :: "r"(9 + cg) : "memory");

        // ---- Epilogue: finalize this pair's 4 columns, publish per-element ----
        if (is_epi) {
            float vv = 0.0f;
            if (lane < 4) {
                float r0 = red[par][0][cg * 4 + lane];
                float r1 = red[par][1][cg * 4 + lane];
                vv = (r0 + r1) * bj;
            }
            if (s == T - 1) {
                float t = (lane < 4) ? vv : 0.0f;
                t += __shfl_xor_sync(0xffffffffu, t, 1);
                t += __shfl_xor_sync(0xffffffffu, t, 2);
                if (lane == 0) {
                    atomicAdd(out, t);
                    unsigned d = atomicAdd(&g_done, 1u);
                    if (d == 4u * GRID - 1u) {
                        *(volatile unsigned*)&g_done  = 0u;
                        *(volatile unsigned*)&g_epoch = epoch + 1u;
                    }
                }
            } else if (lane < 4) {
                st_cg_v2(reinterpret_cast<char*>(g_alpha3[bufW]) + (size_t)(jb + lane) * 8,
                         __float_as_uint(vv), tagW);
            }
        }
        // No trailing barrier: alpha_sm/red are parity double-buffered; a
        // poller's step-(s+2) restripe sits behind its step-(s+1) last foreign
        // stage bar.sync, whose release requires every consumer warp's arrival
        // there, which follows their step-s reads.
    }
}

extern "C" void kernel_launch(void* const* d_in, const int* in_sizes, int n_in,
                              void* d_out, int out_size) {
    const int*   obs = (const int*)d_in[0];
    const float* A   = (const float*)d_in[1];
    const float* B   = (const float*)d_in[2];
    const float* pi  = (const float*)d_in[3];
    float*       out = (float*)d_out;
    (void)in_sizes; (void)n_in; (void)out_size;

    hmm_forward_kernel<<<GRID, NT>>>(obs, A, B, pi, out);
}

// round 17
// speedup vs baseline: 1.0806x; 1.0806x over previous
#include <cuda_runtime.h>

// HMM forward: alpha_t = (alpha_{t-1} @ A) * B[:, obs_t],  out = sum(alpha_{T-1})
// R17 = R6 (best, 5664.8us) with ONE instruction-level change: the poll loads
// use ld.relaxed.gpu (LDG.E.STRONG.GPU) instead of ld.volatile
// (LDG.E.STRONG.SYS). SYS scope orders against the cross-die/host domain on
// the dual-die B300; GPU scope is the cheaper L2 path. All correctness
// properties are unchanged: tags are carried in-band with the value by a
// single 64-bit store, detection is by tag match, the asm volatile block
// forces re-issue each poll iteration.

namespace {
constexpr int GRID = 128;
constexpr int NT   = 256;
constexpr int S    = 2048;
constexpr int V    = 32768;
constexpr int T    = 4096;
constexpr int NCOL = 16;      // columns per block
}

typedef unsigned long long u64;

// Each uint4 = two elements: (val0, tag0, val1, tag1). 3 rotating buffers.
__device__ uint4    g_alpha3[3][S / 2];
__device__ unsigned g_epoch = 0;
__device__ unsigned g_done  = 0;

__device__ __forceinline__ uint4 ld_rlx4(const uint4* p) {
    uint4 v;
    asm volatile("ld.relaxed.gpu.global.v4.u32 {%0,%1,%2,%3}, [%4];"
                 : "=r"(v.x), "=r"(v.y), "=r"(v.z), "=r"(v.w) : "l"(p) : "memory");
    return v;
}
__device__ __forceinline__ void st_cg_v2(void* p, unsigned a, unsigned b) {
    asm volatile("st.global.cg.v2.u32 [%0], {%1,%2};" :: "l"(p), "r"(a), "r"(b) : "memory");
}
__device__ __forceinline__ u64 pack2(float a, float b) {
    u64 d;
    asm("mov.b64 %0, {%1,%2};" : "=l"(d) : "f"(a), "f"(b));
    return d;
}
__device__ __forceinline__ u64 fma2(u64 a, u64 b, u64 c) {
    u64 d;
    asm("fma.rn.f32x2 %0, %1, %2, %3;" : "=l"(d) : "l"(a), "l"(b), "l"(c));
    return d;
}
__device__ __forceinline__ u64 add2(u64 a, u64 b) {
    u64 d;
    asm("add.rn.f32x2 %0, %1, %2;" : "=l"(d) : "l"(a), "l"(b));
    return d;
}

__global__ void __launch_bounds__(NT, 1) hmm_forward_kernel(
    const int*   __restrict__ obs,
    const float* __restrict__ A,
    const float* __restrict__ B,
    const float* __restrict__ pi,
    float*       __restrict__ out)
{
    __shared__ __align__(16) float alpha_sm[2][2][1024]; // [parity][half][elem]
    __shared__ __align__(16) float red[2][2][NCOL];      // [parity][rowgroup][col]

    const int tid  = threadIdx.x;
    const int blk  = blockIdx.x;
    const int w    = tid >> 5;
    const int lane = tid & 31;
    const int cg   = w & 3;               // column group 0..3 (4 cols each)
    const int rg   = w >> 2;              // row group 0..1 (half = 1024 rows)
    const int jb   = blk * NCOL + cg * 4; // first of this warp's 4 columns

    // Pollers: w2 (h0 qA: chunks 0-7), w3 (h0 qB: 8-15), w4 (h1 qA), w5 (h1 qB).
    const bool is_poller = (w >= 2) && (w <= 5);
    const int  poll_half = (w <= 3) ? 0 : 1;
    const int  chunk_off = (w == 2 || w == 4) ? 0 : 8;
    const bool is_qA     = (w == 2 || w == 4);
    // Quarter barriers: half0 -> bars 1(qA),2(qB); half1 -> bars 3(qA),4(qB).
    const int  barA = 1 + rg * 2;
    const int  barB = 2 + rg * 2;
    // Epilogue warp per pair (cg): pair0->w0, pair1->w1, pair2->w6, pair3->w7.
    const bool is_epi = (rg == 0) ? (cg <= 1) : (cg >= 2);

    // ---- Load A tile into packed-pair registers (one time) ----
    // Thread covers rows rg*1024 + 4*lane + 128*k + rr (k<8, rr<4), cols jb..jb+3.
    u64 areg_lo[8][4], areg_hi[8][4];
#pragma unroll
    for (int k = 0; k < 8; k++) {
#pragma unroll
        for (int rr = 0; rr < 4; rr++) {
            int row = rg * 1024 + 4 * lane + 128 * k + rr;
            float4 a4 = *reinterpret_cast<const float4*>(&A[(size_t)row * S + jb]);
            areg_lo[k][rr] = pack2(a4.x, a4.y);
            areg_hi[k][rr] = pack2(a4.z, a4.w);
        }
    }

    const unsigned epoch = *(volatile unsigned*)&g_epoch;
    const unsigned tagbase = epoch * 4096u + 1u;   // >0, unique across replays

    if (blk == 0 && tid == 0) *out = 0.0f;

    // ---- Publish alpha_0 = pi * B[:, obs[0]] with tag(0) ----
    if (is_epi && lane < 4) {
        int   c  = jb + lane;
        int   o0 = __ldg(&obs[0]);
        float v  = pi[c] * __ldg(&B[(size_t)c * V + o0]);
        st_cg_v2(reinterpret_cast<char*>(g_alpha3[0]) + (size_t)c * 8,
                 __float_as_uint(v), tagbase);
    }

    for (int s = 1; s < T; s++) {
        const int      par  = s & 1;
        const int      bufR = (s - 1) % 3;
        const int      bufW = s % 3;
        const unsigned tagR = tagbase + (unsigned)(s - 1);
        const unsigned tagW = tagbase + (unsigned)s;

        // Epilogue lanes prefetch their emission factor (independent of alpha).
        float bj = 0.0f;
        if (is_epi && lane < 4) {
            int o = __ldg(&obs[s]);
            bj = __ldg(&B[(size_t)(jb + lane) * V + o]);
        }

        // ---- Pollers: wait for this quarter's 8 chunks, restripe to SMEM ----
        if (is_poller) {
            const uint4* base = &g_alpha3[bufR][poll_half * 512] + chunk_off * 32 + lane;
            uint4 v[8];
            for (;;) {
                bool ok = true;
#pragma unroll
                for (int c = 0; c < 8; c++) {
                    v[c] = ld_rlx4(base + c * 32);
                    ok &= (v[c].y == tagR) & (v[c].w == tagR);
                }
                if (__all_sync(0xffffffffu, ok)) break;
            }
#pragma unroll
            for (int c = 0; c < 8; c++) {
                float2 f = make_float2(__uint_as_float(v[c].x), __uint_as_float(v[c].z));
                *reinterpret_cast<float2*>(
                    &alpha_sm[par][poll_half][(chunk_off + c) * 64 + 2 * lane]) = f;
            }
            // Publish my quarter to the other 3 warps of this half.
            if (is_qA) asm volatile("bar.arrive %0, 128;" :: "r"(barA) : "memory");
            else       asm volatile("bar.arrive %0, 128;" :: "r"(barB) : "memory");
        }

        const float4* sm4 = reinterpret_cast<const float4*>(alpha_sm[par][rg]);
        u64 acc01 = 0, acc23 = 0;   // packed (col0,col1), (col2,col3)

        // Quarter A (k=0..3): qA poller has its own data; others sync.
        if (!(is_poller && is_qA))
            asm volatile("bar.sync %0, 128;" :: "r"(barA) : "memory");
#pragma unroll
        for (int k = 0; k < 4; k++) {
            float4 av = sm4[k * 32 + lane];
            u64 ax = pack2(av.x, av.x), ay = pack2(av.y, av.y);
            u64 az = pack2(av.z, av.z), aw = pack2(av.w, av.w);
            acc01 = fma2(ax, areg_lo[k][0], acc01);
            acc23 = fma2(ax, areg_hi[k][0], acc23);
            acc01 = fma2(ay, areg_lo[k][1], acc01);
            acc23 = fma2(ay, areg_hi[k][1], acc23);
            acc01 = fma2(az, areg_lo[k][2], acc01);
            acc23 = fma2(az, areg_hi[k][2], acc23);
            acc01 = fma2(aw, areg_lo[k][3], acc01);
            acc23 = fma2(aw, areg_hi[k][3], acc23);
        }
        // Quarter B (k=4..7): qB poller already has its data.
        if (!(is_poller && !is_qA))
            asm volatile("bar.sync %0, 128;" :: "r"(barB) : "memory");
#pragma unroll
        for (int k = 4; k < 8; k++) {
            float4 av = sm4[k * 32 + lane];
            u64 ax = pack2(av.x, av.x), ay = pack2(av.y, av.y);
            u64 az = pack2(av.z, av.z), aw = pack2(av.w, av.w);
            acc01 = fma2(ax, areg_lo[k][0], acc01);
            acc23 = fma2(ax, areg_hi[k][0], acc23);
            acc01 = fma2(ay, areg_lo[k][1], acc01);
            acc23 = fma2(ay, areg_hi[k][1], acc23);
            acc01 = fma2(az, areg_lo[k][2], acc01);
            acc23 = fma2(az, areg_hi[k][2], acc23);
            acc01 = fma2(aw, areg_lo[k][3], acc01);
            acc23 = fma2(aw, areg_hi[k][3], acc23);
        }

        // Warp reduce (rows split across lanes) on packed pairs.
#pragma unroll
        for (int off = 16; off > 0; off >>= 1) {
            acc01 = add2(acc01, __shfl_xor_sync(0xffffffffu, acc01, off));
            acc23 = add2(acc23, __shfl_xor_sync(0xffffffffu, acc23, off));
        }
        if (lane == 0) {
            u64* r = reinterpret_cast<u64*>(&red[par][rg][cg * 4]);
            r[0] = acc01;
            r[1] = acc23;
        }

        // Pair-scoped barrier: warps (cg, cg+4) on bar 5+cg, 64 threads.
        asm volatile("bar.sync %0, 64;" :: "r"(5 + cg) : "memory");

        // ---- Epilogue: finalize this pair's 4 columns, publish per-element ----
        if (is_epi) {
            float vv = 0.0f;
            if (lane < 4) {
                float r0 = red[par][0][cg * 4 + lane];
                float r1 = red[par][1][cg * 4 + lane];
                vv = (r0 + r1) * bj;
            }
            if (s == T - 1) {
                float t = (lane < 4) ? vv : 0.0f;
                t += __shfl_xor_sync(0xffffffffu, t, 1);
                t += __shfl_xor_sync(0xffffffffu, t, 2);
                if (lane == 0) {
                    atomicAdd(out, t);
                    unsigned d = atomicAdd(&g_done, 1u);
                    if (d == 4u * GRID - 1u) {
                        *(volatile unsigned*)&g_done  = 0u;
                        *(volatile unsigned*)&g_epoch = epoch + 1u;
                    }
                }
            } else if (lane < 4) {
                st_cg_v2(reinterpret_cast<char*>(g_alpha3[bufW]) + (size_t)(jb + lane) * 8,
                         __float_as_uint(vv), tagW);
            }
        }
        // No trailing barrier: alpha_sm/red are parity double-buffered; the
        // publish->consume->barrier chain guarantees step-s readers finish
        // before step-(s+2) writers of the same parity slot can start.
    }
}

extern "C" void kernel_launch(void* const* d_in, const int* in_sizes, int n_in,
                              void* d_out, int out_size) {
    const int*   obs = (const int*)d_in[0];
    const float* A   = (const float*)d_in[1];
    const float* B   = (const float*)d_in[2];
    const float* pi  = (const float*)d_in[3];
    float*       out = (float*)d_out;
    (void)in_sizes; (void)n_in; (void)out_size;

    hmm_forward_kernel<<<GRID, NT>>>(obs, A, B, pi, out);
}